// round 12
// baseline (speedup 1.0000x reference)
#include <cuda_runtime.h>
#include <cuda_fp16.h>
#include <cstdint>

#define TOK   4096
#define DIMN  512
#define GQ    32
#define HD    16
#define RNUM  4
#define INTER 405
#define INTP  408
#define DIN1  144
#define H1LD  576
#define HSLDP 1632
#define NSEQ  512

// ---------------- device scratch (fp16 payloads) ----------------
__device__ __half g_xc[TOK * DIMN];
__device__ __half g_wqt[DIMN * DIMN];     // [n][k]
__device__ __half g_wkt[DIMN * DIMN];
__device__ __half g_wvt[DIMN * DIMN];
__device__ __half g_wint[64 * DIMN];
__device__ __half g_w1t[RNUM * INTP * DIN1];   // per rule [408][144]
__device__ __half g_w2t[DIMN * HSLDP];         // [512][1632], pad k zero
__device__ __half g_qkv[3 * TOK * DIMN];
__device__ __half g_h1[TOK * H1LD];
__device__ __half g_hs[TOK * HSLDP];

// ---------------- helpers ----------------
__device__ __forceinline__ uint32_t smem_u32(const void* p) {
    uint32_t a;
    asm("{ .reg .u64 t; cvta.to.shared.u64 t, %1; cvt.u32.u64 %0, t; }"
        : "=r"(a) : "l"(p));
    return a;
}
__device__ __forceinline__ void cp16(uint32_t dst, const void* src, bool pred) {
    int sz = pred ? 16 : 0;
    asm volatile("cp.async.ca.shared.global [%0], [%1], 16, %2;"
                 :: "r"(dst), "l"(src), "r"(sz) : "memory");
}
#define CP_COMMIT() asm volatile("cp.async.commit_group;" ::: "memory")
#define CP_WAIT1()  asm volatile("cp.async.wait_group 1;" ::: "memory")
#define CP_WAIT0()  asm volatile("cp.async.wait_group 0;" ::: "memory")

__device__ __forceinline__ void mma_f16(float d[4], const uint32_t a[4],
                                        const uint32_t b[2]) {
    asm volatile(
        "mma.sync.aligned.m16n8k16.row.col.f32.f16.f16.f32 "
        "{%0,%1,%2,%3}, {%4,%5,%6,%7}, {%8,%9}, {%0,%1,%2,%3};"
        : "+f"(d[0]), "+f"(d[1]), "+f"(d[2]), "+f"(d[3])
        : "r"(a[0]), "r"(a[1]), "r"(a[2]), "r"(a[3]), "r"(b[0]), "r"(b[1]));
}
__device__ __forceinline__ void ldsm_x4(uint32_t& r0, uint32_t& r1,
                                        uint32_t& r2, uint32_t& r3, uint32_t addr) {
    asm volatile("ldmatrix.sync.aligned.m8n8.x4.shared.b16 {%0,%1,%2,%3}, [%4];"
                 : "=r"(r0), "=r"(r1), "=r"(r2), "=r"(r3) : "r"(addr));
}
__device__ __forceinline__ float ex2(float s) {
    float r;
    asm("ex2.approx.f32 %0, %1;" : "=f"(r) : "f"(s));
    return r;
}

// ---------------- one-shot conversion + weight transposes ----------------
__device__ void trans_tile(const float* __restrict__ src, __half* __restrict__ dst,
                           int K, int N, int ldk, int tk, int tn, bool w2remap)
{
    __shared__ float tl[32][33];
    int tx = threadIdx.x & 31, ty = threadIdx.x >> 5;
    int k0 = tk * 32, n0 = tn * 32;
#pragma unroll
    for (int i = 0; i < 4; i++) {
        int k = k0 + ty + i * 8, n = n0 + tx;
        tl[ty + i * 8][tx] = (k < K && n < N) ? src[(size_t)k * N + n] : 0.f;
    }
    __syncthreads();
#pragma unroll
    for (int i = 0; i < 4; i++) {
        int n = n0 + ty + i * 8, k = k0 + tx;
        if (n < N && k < K) {
            int kk = w2remap ? k + 3 * (k / 405) : k;
            dst[(size_t)n * ldk + kk] = __float2half_rn(tl[tx][ty + i * 8]);
        }
    }
}

__global__ void conv_all(const float* __restrict__ x,  const float* __restrict__ Wq,
                         const float* __restrict__ Wk, const float* __restrict__ Wv,
                         const float* __restrict__ Win, const float* __restrict__ W1,
                         const float* __restrict__ W2)
{
    int b = blockIdx.x;
    if (b < 256) {
#pragma unroll
        for (int u = 0; u < 32; u++) {
            int i = b * 8192 + u * 256 + threadIdx.x;
            g_xc[i] = __float2half_rn(x[i]);
        }
    } else if (b < 512) {
        int i = b - 256;  trans_tile(Wq, g_wqt, 512, 512, 512, i / 16, i % 16, false);
    } else if (b < 768) {
        int i = b - 512;  trans_tile(Wk, g_wkt, 512, 512, 512, i / 16, i % 16, false);
    } else if (b < 1024) {
        int i = b - 768;  trans_tile(Wv, g_wvt, 512, 512, 512, i / 16, i % 16, false);
    } else if (b < 1056) {
        int i = b - 1024; trans_tile(Win, g_wint, 512, 64, 512, i / 2, i % 2, false);
    } else if (b < 1316) {
        int i = b - 1056; int r = i / 65, rem = i % 65;
        trans_tile(W1 + (size_t)r * DIN1 * INTER, g_w1t + (size_t)r * INTP * DIN1,
                   DIN1, INTER, DIN1, rem / 13, rem % 13, false);
    } else {
        int i = b - 1316;
        trans_tile(W2, g_w2t, 1620, 512, HSLDP, i / 16, i % 16, true);
    }
}

// ============================================================
// Fused QKV + in_proj: A (x m-strip, full K=512) resident in smem,
// z-loop streams only B chunks. CTA 128x128, 8 warps, warp 32x64.
// Cuts mode-0 cp.async traffic 98MB -> 66MB.
// ============================================================
#define ALD   520                      /* A row stride in halves */
#define QSM_A (128 * ALD)              /* 66560 halves */
#define BLD   72
#define QSM_B (128 * BLD)              /* per stage, 9216 halves */
#define QKV_SMEM ((QSM_A + 2 * QSM_B) * 2)   /* 169984 bytes */

__global__ void __launch_bounds__(256, 1) qkv_fused(
    const float* __restrict__ bq, const float* __restrict__ bk,
    const float* __restrict__ bv, const float* __restrict__ b_in)
{
    extern __shared__ __half dynsh[];
    const uint32_t smA = smem_u32(dynsh);
    const uint32_t smB = smA + (uint32_t)QSM_A * 2u;

    const int tid = threadIdx.x;
    const int wid = tid >> 5, lane = tid & 31;
    const int wm = wid >> 1, wn = wid & 1;
    const int g = lane >> 2, tq = lane & 3;
    const int l8 = lane & 7, lm = lane >> 3;
    const int m_base = blockIdx.y * 128;
    const int n_base = blockIdx.x * 128;

    const __half* A = g_xc + (size_t)m_base * DIMN;
    const __half* Bz[4] = { g_wqt, g_wkt, g_wvt, g_wint };
    const float* biasz[4] = { bq, bk, bv, b_in };
    const int NC = (blockIdx.x == 0) ? 32 : 24;   // 8 chunks per z

    // ldmatrix offsets
    const uint32_t offA0 = (uint32_t)(((wm * 32 + (lm & 1) * 8 + l8) * ALD
                                       + (lm >> 1) * 8) * 2);
    const uint32_t offA1 = offA0 + (uint32_t)(16 * ALD * 2);
    uint32_t offB[4];
#pragma unroll
    for (int jj = 0; jj < 4; jj++)
        offB[jj] = (uint32_t)(((wn * 64 + jj * 16 + (lm >> 1) * 8 + l8) * BLD
                               + (lm & 1) * 8) * 2);

    // B chunk issue: chunk c -> z = c>>3, t = c&7, buffer c&1
#define ISSUE_B(c)                                                             \
    do {                                                                       \
        int z_ = (c) >> 3, t_ = (c) & 7;                                       \
        const __half* Bp = Bz[z_];                                             \
        int nrows = (z_ == 3) ? 64 : 512;                                      \
        uint32_t sB = smB + (uint32_t)(((c) & 1) * QSM_B) * 2u;                \
        _Pragma("unroll")                                                      \
        for (int i = 0; i < 4; i++) {                                          \
            int idx = tid + (i << 8);                                          \
            int row = idx >> 3, grp = idx & 7;                                 \
            int nr = n_base + row;                                             \
            bool pb = nr < nrows;                                              \
            int brow = pb ? nr : 0;                                            \
            cp16(sB + (uint32_t)(row * BLD + grp * 8) * 2u,                    \
                 Bp + (size_t)brow * DIMN + t_ * 64 + grp * 8, pb);            \
        }                                                                      \
        CP_COMMIT();                                                           \
    } while (0)

    // prologue: B chunk 0, 1, then resident A (8192 cp16 = 32/thread)
    ISSUE_B(0);
    ISSUE_B(1);
#pragma unroll
    for (int i = 0; i < 32; i++) {
        int idx = tid + (i << 8);
        int row = idx >> 6, grp = idx & 63;
        cp16(smA + (uint32_t)(row * ALD + grp * 8) * 2u,
             A + (size_t)row * DIMN + grp * 8, true);
    }
    CP_COMMIT();
    CP_WAIT0();
    __syncthreads();

    float d[2][8][4];
#pragma unroll
    for (int i = 0; i < 2; i++)
#pragma unroll
        for (int j = 0; j < 8; j++)
#pragma unroll
            for (int c = 0; c < 4; c++) d[i][j][c] = 0.f;

    for (int c = 0; c < NC; c++) {
        const int z = c >> 3, t = c & 7;
        const uint32_t bB = smB + (uint32_t)((c & 1) * QSM_B) * 2u;
#pragma unroll
        for (int ks = 0; ks < 4; ks++) {
            const uint32_t kofB = (uint32_t)(ks * 32);
            const uint32_t kofA = (uint32_t)((t * 64 + ks * 16) * 2);
            uint32_t bf[8][2];
#pragma unroll
            for (int jj = 0; jj < 4; jj++)
                ldsm_x4(bf[2 * jj][0], bf[2 * jj][1],
                        bf[2 * jj + 1][0], bf[2 * jj + 1][1], bB + offB[jj] + kofB);
            uint32_t af0[4], af1[4];
            ldsm_x4(af0[0], af0[1], af0[2], af0[3], smA + offA0 + kofA);
            ldsm_x4(af1[0], af1[1], af1[2], af1[3], smA + offA1 + kofA);
#pragma unroll
            for (int j = 0; j < 8; j++) {
                mma_f16(d[0][j], af0, bf[j]);
                mma_f16(d[1][j], af1, bf[j]);
            }
        }

        if (t == 7) {
            // epilogue for this z from registers
            const float* bias = biasz[z];
#pragma unroll
            for (int i = 0; i < 2; i++) {
                int mr[2];
                mr[0] = m_base + wm * 32 + i * 16 + g;
                mr[1] = mr[0] + 8;
#pragma unroll
                for (int j = 0; j < 8; j++) {
                    int n0 = n_base + wn * 64 + j * 8 + tq * 2;
#pragma unroll
                    for (int rr = 0; rr < 2; rr++) {
                        float v0 = d[i][j][rr * 2 + 0];
                        float v1 = d[i][j][rr * 2 + 1];
                        int m = mr[rr];
                        if (z == 3) {
                            if (n0 < 64) {
                                int r0i = n0 >> 4, d0i = n0 & 15;
                                int r1i = (n0 + 1) >> 4, d1i = (n0 + 1) & 15;
                                g_h1[(size_t)m * H1LD + r0i * DIN1 + 128 + d0i] =
                                    __float2half_rn(v0 + bias[n0]);
                                g_h1[(size_t)m * H1LD + r1i * DIN1 + 128 + d1i] =
                                    __float2half_rn(v1 + bias[n0 + 1]);
                            }
                        } else {
                            __half* C = g_qkv + (size_t)z * TOK * DIMN;
                            *(__half2*)(C + (size_t)m * DIMN + n0) =
                                __floats2half2_rn(v0 + bias[n0], v1 + bias[n0 + 1]);
                        }
                        d[i][j][rr * 2 + 0] = 0.f;
                        d[i][j][rr * 2 + 1] = 0.f;
                    }
                }
            }
        }

        __syncthreads();
        if (c + 2 < NC) ISSUE_B(c + 2);
        if (c + 1 < NC) {
            if (c + 2 < NC) CP_WAIT1(); else CP_WAIT0();
            __syncthreads();
        }
    }
#undef ISSUE_B
}

// ============================================================
// fp16 mma GEMM (unchanged, modes 2 and 3 only)
// ============================================================
#define KC     64
#define LDH    72
#define ABUFH  (128 * LDH)
#define BBUFH  (128 * LDH)
#define BUFH   (ABUFH + BBUFH)
#define GEMM_SMEM (2 * BUFH * 2)

template<int MODE>
__global__ void __launch_bounds__(256, 2) mma_gemm(
    const float* __restrict__ b1, const float* __restrict__ b2,
    const float* __restrict__ rs, float* __restrict__ out)
{
    extern __shared__ __half dynsh[];
    const uint32_t smbase = smem_u32(dynsh);

    const int tid = threadIdx.x;
    const int wid = tid >> 5, lane = tid & 31;
    const int wm = wid >> 1, wn = wid & 1;
    const int g = lane >> 2, tq = lane & 3;
    const int m_base = blockIdx.y * 128;
    const int n_base = blockIdx.x * 128;
    const int z = blockIdx.z;

    const __half* A; const __half* Bt; const float* bias;
    int lda, K, Nrows, ldbk;
    if (MODE == 2) {
        A = g_h1 + (size_t)m_base * H1LD + z * DIN1; lda = H1LD; K = DIN1;
        Bt = g_w1t + (size_t)z * INTP * DIN1; Nrows = INTP; ldbk = DIN1;
        bias = b1 + z * INTER;
    } else {
        A = g_hs + (size_t)m_base * HSLDP; lda = HSLDP; K = HSLDP;
        Bt = g_w2t; Nrows = 512; ldbk = HSLDP; bias = b2;
    }

    float d[2][8][4];
#pragma unroll
    for (int i = 0; i < 2; i++)
#pragma unroll
        for (int j = 0; j < 8; j++)
#pragma unroll
            for (int c = 0; c < 4; c++) d[i][j][c] = 0.f;

    const int KT = (K + KC - 1) / KC;

    const int l8 = lane & 7, lm = lane >> 3;
    const uint32_t offA0 = (uint32_t)(((wm * 32 + (lm & 1) * 8 + l8) * LDH
                                       + (lm >> 1) * 8) * 2);
    const uint32_t offA1 = offA0 + (uint32_t)(16 * LDH * 2);
    uint32_t offB[4];
#pragma unroll
    for (int jj = 0; jj < 4; jj++)
        offB[jj] = (uint32_t)(((wn * 64 + jj * 16 + (lm >> 1) * 8 + l8) * LDH
                               + (lm & 1) * 8) * 2);

#define ISSUE(k0, buf)                                                         \
    do {                                                                       \
        uint32_t sA = smbase + (uint32_t)((buf) * BUFH) * 2u;                  \
        uint32_t sB = sA + (uint32_t)ABUFH * 2u;                               \
        _Pragma("unroll")                                                      \
        for (int i = 0; i < 4; i++) {                                          \
            int idx = tid + (i << 8);                                          \
            int row = idx >> 3, grp = idx & 7;                                 \
            int kk = (k0) + grp * 8;                                           \
            bool pk = kk < K;                                                  \
            int kcl = pk ? kk : 0;                                             \
            cp16(sA + (uint32_t)(row * LDH + grp * 8) * 2u,                    \
                 A + (size_t)row * lda + kcl, pk);                             \
            bool pb = pk && (n_base + row) < Nrows;                            \
            int brow = ((n_base + row) < Nrows) ? (n_base + row) : 0;          \
            cp16(sB + (uint32_t)(row * LDH + grp * 8) * 2u,                    \
                 Bt + (size_t)brow * ldbk + kcl, pb);                          \
        }                                                                      \
    } while (0)

    ISSUE(0, 0);
    CP_COMMIT();
    ISSUE(KC, 1);
    CP_COMMIT();
    CP_WAIT1();
    __syncthreads();

    for (int t = 0; t < KT; t++) {
        const uint32_t aB = smbase + (uint32_t)((t & 1) * BUFH) * 2u;
        const uint32_t bB = aB + (uint32_t)ABUFH * 2u;
#pragma unroll
        for (int ks = 0; ks < 4; ks++) {
            const uint32_t kof = (uint32_t)(ks * 32);
            uint32_t bf[8][2];
#pragma unroll
            for (int jj = 0; jj < 4; jj++)
                ldsm_x4(bf[2 * jj][0], bf[2 * jj][1],
                        bf[2 * jj + 1][0], bf[2 * jj + 1][1], bB + offB[jj] + kof);
            uint32_t af0[4], af1[4];
            ldsm_x4(af0[0], af0[1], af0[2], af0[3], aB + offA0 + kof);
            ldsm_x4(af1[0], af1[1], af1[2], af1[3], aB + offA1 + kof);
#pragma unroll
            for (int j = 0; j < 8; j++) {
                mma_f16(d[0][j], af0, bf[j]);
                mma_f16(d[1][j], af1, bf[j]);
            }
        }
        __syncthreads();
        if (t + 2 < KT) { ISSUE((t + 2) * KC, t & 1); CP_COMMIT(); }
        if (t + 1 < KT) {
            if (t + 2 < KT) CP_WAIT1(); else CP_WAIT0();
            __syncthreads();
        }
    }

#pragma unroll
    for (int i = 0; i < 2; i++) {
        int mr[2];
        mr[0] = m_base + wm * 32 + i * 16 + g;
        mr[1] = mr[0] + 8;
#pragma unroll
        for (int j = 0; j < 8; j++) {
            int n0 = n_base + wn * 64 + j * 8 + tq * 2;
#pragma unroll
            for (int rr = 0; rr < 2; rr++) {
                float v0 = d[i][j][rr * 2 + 0];
                float v1 = d[i][j][rr * 2 + 1];
                int m = mr[rr];
                if (MODE == 2) {
                    float rsv = rs[m * RNUM + z];
                    size_t base = (size_t)m * HSLDP + z * INTP + n0;
                    if (n0 + 1 < INTER) {
                        *(__half2*)(g_hs + base) = __floats2half2_rn(
                            fmaxf(v0 + bias[n0], 0.f) * rsv,
                            fmaxf(v1 + bias[n0 + 1], 0.f) * rsv);
                    } else if (n0 < INTER) {
                        g_hs[base] = __float2half_rn(fmaxf(v0 + bias[n0], 0.f) * rsv);
                    }
                } else {
                    float4 q = *(const float4*)(rs + m * RNUM);
                    float b0 = q.x * bias[n0]            + q.y * bias[DIMN + n0]
                             + q.z * bias[2 * DIMN + n0] + q.w * bias[3 * DIMN + n0];
                    float b1v = q.x * bias[n0 + 1]            + q.y * bias[DIMN + n0 + 1]
                              + q.z * bias[2 * DIMN + n0 + 1] + q.w * bias[3 * DIMN + n0 + 1];
                    *(float2*)(out + (size_t)m * DIMN + n0) =
                        make_float2(v0 + b0, v1 + b1v);
                }
            }
        }
    }

    if (MODE == 3 && blockIdx.x == 0) {
        int idx = blockIdx.y * 512 + tid * 2;
        *(float2*)(out + (size_t)TOK * DIMN + idx) = *(const float2*)(rs + idx);
    }
#undef ISSUE
}

// ============================================================
// Flash attention (unchanged from R11).
// ============================================================
#define LDQH 24
#define LDPH 136
#define FA_SMEM ((128 * LDQH * 2 + 16 * LDPH + 128 * LDPH) * 2)
#define QK_SCALE 0.360673760222241f

__global__ void __launch_bounds__(256, 2) fa_kernel()
{
    extern __shared__ __half fsh[];
    __half* Qs = fsh;
    __half* Ks = fsh + 128 * LDQH;
    __half* Vs = fsh + 2 * 128 * LDQH;
    __half* Ps = Vs + 16 * LDPH;
    const uint32_t uQs = smem_u32(Qs);
    const uint32_t uKs = smem_u32(Ks);
    const uint32_t uVs = smem_u32(Vs);
    const uint32_t uPs = smem_u32(Ps);

    const int qt = blockIdx.x;
    const int gg = blockIdx.y;
    const int bb = blockIdx.z;
    const int r = gg >> 3, hh = gg & 7;
    const int tid = threadIdx.x;
    const int wid = tid >> 5, lane = tid & 31;
    const int g = lane >> 2, tq = lane & 3;
    const int l8 = lane & 7, lm = lane >> 3;

    const __half* gq = g_qkv;
    const __half* gk = g_qkv + (size_t)TOK * DIMN;
    const __half* gv = g_qkv + 2 * (size_t)TOK * DIMN;
    const int seq0 = bb * NSEQ;

    const __half2 qscale = __floats2half2_rn(QK_SCALE, QK_SCALE);

    {
        int row = tid >> 1, part = tid & 1;
        int tok = seq0 + qt * 128 + row;
        uint4 v = *(const uint4*)(gq + (size_t)tok * DIMN + gg * HD + part * 8);
        __half2* pv = (__half2*)&v;
#pragma unroll
        for (int l = 0; l < 4; l++) pv[l] = __hmul2(pv[l], qscale);
        *(uint4*)(Qs + row * LDQH + part * 8) = v;
    }

    float o[2][4];
#pragma unroll
    for (int j = 0; j < 2; j++)
#pragma unroll
        for (int c = 0; c < 4; c++) o[j][c] = 0.f;
    float lsum[2] = {0.f, 0.f};

    const int row0 = wid * 16 + g;

    const uint32_t offQA = (uint32_t)(((wid * 16 + (lm & 1) * 8 + l8) * LDQH
                                       + (lm >> 1) * 8) * 2);
    uint32_t offKB[4];
#pragma unroll
    for (int jj = 0; jj < 4; jj++)
        offKB[jj] = (uint32_t)(((jj * 16 + (lm >> 1) * 8 + l8) * LDQH
                                + (lm & 1) * 8) * 2);
    const uint32_t offPA = (uint32_t)(((wid * 16 + (lm & 1) * 8 + l8) * LDPH
                                       + (lm >> 1) * 8) * 2);
    const uint32_t offVB = (uint32_t)((((lm >> 1) * 8 + l8) * LDPH
                                       + (lm & 1) * 8) * 2);

    for (int jt = 0; jt < 4; jt++) {
        {
            int row = tid >> 1, part = tid & 1;
            int tok = seq0 + jt * 128 + row;
            uint4 kv = *(const uint4*)(gk + (size_t)tok * DIMN + gg * HD + part * 8);
            *(uint4*)(Ks + row * LDQH + part * 8) = kv;
            uint4 vv = *(const uint4*)(gv + (size_t)tok * DIMN + gg * HD + part * 8);
            __half tmp[8];
            *(uint4*)tmp = vv;
            int d0 = part * 8;
#pragma unroll
            for (int l = 0; l < 8; l++) Vs[(d0 + l) * LDPH + row] = tmp[l];
        }
        __syncthreads();

        uint32_t af[4];
        ldsm_x4(af[0], af[1], af[2], af[3], uQs + offQA);

#pragma unroll
        for (int hn = 0; hn < 2; hn++) {
            const uint32_t hof = (uint32_t)(hn * 64 * LDQH * 2);
            uint32_t bf[8][2];
#pragma unroll
            for (int jj = 0; jj < 4; jj++)
                ldsm_x4(bf[2 * jj][0], bf[2 * jj][1],
                        bf[2 * jj + 1][0], bf[2 * jj + 1][1],
                        uKs + offKB[jj] + hof);
            float s[8][4];
#pragma unroll
            for (int jn = 0; jn < 8; jn++) {
#pragma unroll
                for (int c = 0; c < 4; c++) s[jn][c] = 0.f;
                mma_f16(s[jn], af, bf[jn]);
            }
#pragma unroll
            for (int jn = 0; jn < 8; jn++) {
                int c0 = hn * 64 + jn * 8 + 2 * tq;
                int gc0 = jt * 128 + c0;
#pragma unroll
                for (int rr = 0; rr < 2; rr++) {
                    int rl = row0 + rr * 8;
                    int grow = qt * 128 + rl;
                    float p0 = ex2(s[jn][rr * 2 + 0]);
                    float p1 = ex2(s[jn][rr * 2 + 1]);
                    if (gc0 == grow)     p0 = 0.f;
                    if (gc0 + 1 == grow) p1 = 0.f;
                    lsum[rr] += p0 + p1;
                    *(__half2*)(Ps + rl * LDPH + c0) = __floats2half2_rn(p0, p1);
                }
            }
        }
        __syncthreads();

#pragma unroll
        for (int ksi = 0; ksi < 8; ksi++) {
            const uint32_t kof = (uint32_t)(ksi * 32);
            uint32_t pa[4];
            ldsm_x4(pa[0], pa[1], pa[2], pa[3], uPs + offPA + kof);
            uint32_t bf[2][2];
            ldsm_x4(bf[0][0], bf[0][1], bf[1][0], bf[1][1], uVs + offVB + kof);
            mma_f16(o[0], pa, bf[0]);
            mma_f16(o[1], pa, bf[1]);
        }
        __syncthreads();
    }

#pragma unroll
    for (int rr = 0; rr < 2; rr++) {
        lsum[rr] += __shfl_xor_sync(0xFFFFFFFF, lsum[rr], 1);
        lsum[rr] += __shfl_xor_sync(0xFFFFFFFF, lsum[rr], 2);
    }
    float inv[2] = {1.f / lsum[0], 1.f / lsum[1]};

#pragma unroll
    for (int rr = 0; rr < 2; rr++) {
        int tok = seq0 + qt * 128 + row0 + rr * 8;
        __half* dst = g_h1 + (size_t)tok * H1LD + r * DIN1 + hh * HD;
#pragma unroll
        for (int jn = 0; jn < 2; jn++) {
            int col = jn * 8 + 2 * tq;
            *(__half2*)(dst + col) = __floats2half2_rn(o[jn][rr * 2 + 0] * inv[rr],
                                                       o[jn][rr * 2 + 1] * inv[rr]);
        }
    }
}

// ============================================================
extern "C" void kernel_launch(void* const* d_in, const int* in_sizes, int n_in,
                              void* d_out, int out_size)
{
    const float* x    = (const float*)d_in[0];
    const float* rs   = (const float*)d_in[1];
    const float* Wq   = (const float*)d_in[2];
    const float* bq   = (const float*)d_in[3];
    const float* Wk   = (const float*)d_in[4];
    const float* bk   = (const float*)d_in[5];
    const float* Wv   = (const float*)d_in[6];
    const float* bv   = (const float*)d_in[7];
    const float* Win  = (const float*)d_in[8];
    const float* b_in = (const float*)d_in[9];
    const float* W1   = (const float*)d_in[10];
    const float* b1   = (const float*)d_in[11];
    const float* W2   = (const float*)d_in[12];
    const float* b2   = (const float*)d_in[13];
    float* out = (float*)d_out;

    cudaFuncSetAttribute(qkv_fused, cudaFuncAttributeMaxDynamicSharedMemorySize, QKV_SMEM);
    cudaFuncSetAttribute(mma_gemm<2>, cudaFuncAttributeMaxDynamicSharedMemorySize, GEMM_SMEM);
    cudaFuncSetAttribute(mma_gemm<3>, cudaFuncAttributeMaxDynamicSharedMemorySize, GEMM_SMEM);
    cudaFuncSetAttribute(fa_kernel, cudaFuncAttributeMaxDynamicSharedMemorySize, FA_SMEM);

    conv_all<<<2132, 256>>>(x, Wq, Wk, Wv, Win, W1, W2);

    qkv_fused<<<dim3(4, 32), 256, QKV_SMEM>>>(bq, bk, bv, b_in);
    fa_kernel<<<dim3(4, GQ, 8), 256, FA_SMEM>>>();
    mma_gemm<2><<<dim3(4, 32, 4), 256, GEMM_SMEM>>>(b1, b2, rs, out);
    mma_gemm<3><<<dim3(4, 32, 1), 256, GEMM_SMEM>>>(b1, b2, rs, out);
}

// round 13
// speedup vs baseline: 1.1769x; 1.1769x over previous
#include <cuda_runtime.h>
#include <cuda_fp16.h>
#include <cstdint>

#define TOK   4096
#define DIMN  512
#define GQ    32
#define HD    16
#define RNUM  4
#define INTER 405
#define INTP  408
#define DIN1  144
#define H1LD  576
#define HSLDP 1632
#define NSEQ  512

// ---------------- device scratch (fp16 payloads) ----------------
__device__ __half g_xc[TOK * DIMN];
__device__ __half g_wqt[DIMN * DIMN];     // [n][k]
__device__ __half g_wkt[DIMN * DIMN];
__device__ __half g_wvt[DIMN * DIMN];
__device__ __half g_wint[64 * DIMN];
__device__ __half g_w1t[RNUM * INTP * DIN1];   // per rule [408][144]
__device__ __half g_w2t[DIMN * HSLDP];         // [512][1632], pad k zero
__device__ __half g_qkv[3 * TOK * DIMN];
__device__ __half g_h1[TOK * H1LD];
__device__ __half g_hs[TOK * HSLDP];

// ---------------- helpers ----------------
__device__ __forceinline__ uint32_t smem_u32(const void* p) {
    uint32_t a;
    asm("{ .reg .u64 t; cvta.to.shared.u64 t, %1; cvt.u32.u64 %0, t; }"
        : "=r"(a) : "l"(p));
    return a;
}
__device__ __forceinline__ void cp16(uint32_t dst, const void* src, bool pred) {
    int sz = pred ? 16 : 0;
    asm volatile("cp.async.ca.shared.global [%0], [%1], 16, %2;"
                 :: "r"(dst), "l"(src), "r"(sz) : "memory");
}
#define CP_COMMIT() asm volatile("cp.async.commit_group;" ::: "memory")
#define CP_WAIT1()  asm volatile("cp.async.wait_group 1;" ::: "memory")
#define CP_WAIT0()  asm volatile("cp.async.wait_group 0;" ::: "memory")

__device__ __forceinline__ void mma_f16(float d[4], const uint32_t a[4],
                                        const uint32_t b[2]) {
    asm volatile(
        "mma.sync.aligned.m16n8k16.row.col.f32.f16.f16.f32 "
        "{%0,%1,%2,%3}, {%4,%5,%6,%7}, {%8,%9}, {%0,%1,%2,%3};"
        : "+f"(d[0]), "+f"(d[1]), "+f"(d[2]), "+f"(d[3])
        : "r"(a[0]), "r"(a[1]), "r"(a[2]), "r"(a[3]), "r"(b[0]), "r"(b[1]));
}
__device__ __forceinline__ void ldsm_x4(uint32_t& r0, uint32_t& r1,
                                        uint32_t& r2, uint32_t& r3, uint32_t addr) {
    asm volatile("ldmatrix.sync.aligned.m8n8.x4.shared.b16 {%0,%1,%2,%3}, [%4];"
                 : "=r"(r0), "=r"(r1), "=r"(r2), "=r"(r3) : "r"(addr));
}
__device__ __forceinline__ float ex2(float s) {
    float r;
    asm("ex2.approx.f32 %0, %1;" : "=f"(r) : "f"(s));
    return r;
}

// ---------------- one-shot conversion + weight transposes ----------------
__device__ void trans_tile(const float* __restrict__ src, __half* __restrict__ dst,
                           int K, int N, int ldk, int tk, int tn, bool w2remap)
{
    __shared__ float tl[32][33];
    int tx = threadIdx.x & 31, ty = threadIdx.x >> 5;
    int k0 = tk * 32, n0 = tn * 32;
#pragma unroll
    for (int i = 0; i < 4; i++) {
        int k = k0 + ty + i * 8, n = n0 + tx;
        tl[ty + i * 8][tx] = (k < K && n < N) ? src[(size_t)k * N + n] : 0.f;
    }
    __syncthreads();
#pragma unroll
    for (int i = 0; i < 4; i++) {
        int n = n0 + ty + i * 8, k = k0 + tx;
        if (n < N && k < K) {
            int kk = w2remap ? k + 3 * (k / 405) : k;
            dst[(size_t)n * ldk + kk] = __float2half_rn(tl[tx][ty + i * 8]);
        }
    }
}

__global__ void conv_all(const float* __restrict__ x,  const float* __restrict__ Wq,
                         const float* __restrict__ Wk, const float* __restrict__ Wv,
                         const float* __restrict__ Win, const float* __restrict__ W1,
                         const float* __restrict__ W2)
{
    int b = blockIdx.x;
    if (b < 256) {
        // vectorized x conversion: 8192 floats per block via float4
#pragma unroll
        for (int u = 0; u < 8; u++) {
            int i = b * 2048 + u * 256 + threadIdx.x;   // float4 index
            float4 v = *(const float4*)(x + (size_t)i * 4);
            __half2 h0 = __floats2half2_rn(v.x, v.y);
            __half2 h1 = __floats2half2_rn(v.z, v.w);
            *(uint32_t*)(g_xc + (size_t)i * 4)     = *(uint32_t*)&h0;
            *(uint32_t*)(g_xc + (size_t)i * 4 + 2) = *(uint32_t*)&h1;
        }
    } else if (b < 512) {
        int i = b - 256;  trans_tile(Wq, g_wqt, 512, 512, 512, i / 16, i % 16, false);
    } else if (b < 768) {
        int i = b - 512;  trans_tile(Wk, g_wkt, 512, 512, 512, i / 16, i % 16, false);
    } else if (b < 1024) {
        int i = b - 768;  trans_tile(Wv, g_wvt, 512, 512, 512, i / 16, i % 16, false);
    } else if (b < 1056) {
        int i = b - 1024; trans_tile(Win, g_wint, 512, 64, 512, i / 2, i % 2, false);
    } else if (b < 1316) {
        int i = b - 1056; int r = i / 65, rem = i % 65;
        trans_tile(W1 + (size_t)r * DIN1 * INTER, g_w1t + (size_t)r * INTP * DIN1,
                   DIN1, INTER, DIN1, rem / 13, rem % 13, false);
    } else {
        int i = b - 1316;
        trans_tile(W2, g_w2t, 1620, 512, HSLDP, i / 16, i % 16, true);
    }
}

// ============================================================
// fp16 mma GEMM (R11 structure): CTA 128x128, KC=64, 8 warps,
// warp tile 32x64, 2-stage cp.async + ldmatrix.x4 fragment loads.
//   MODE 0: z=0..2 q/k/v; z=3 in_proj (N=64, bx==0)
//   MODE 2: MLP1 per rule z (K=144)
//   MODE 3: MLP2 (K=1632 padded, +sum_r rs*b2 -> out) + rs tail
// ============================================================
#define KC     64
#define LDH    72
#define ABUFH  (128 * LDH)
#define BBUFH  (128 * LDH)
#define BUFH   (ABUFH + BBUFH)
#define GEMM_SMEM (2 * BUFH * 2)

template<int MODE>
__global__ void __launch_bounds__(256, 2) mma_gemm(
    const float* __restrict__ bq, const float* __restrict__ bk,
    const float* __restrict__ bv, const float* __restrict__ b_in,
    const float* __restrict__ b1, const float* __restrict__ b2,
    const float* __restrict__ rs, float* __restrict__ out)
{
    extern __shared__ __half dynsh[];
    const uint32_t smbase = smem_u32(dynsh);

    const int tid = threadIdx.x;
    const int wid = tid >> 5, lane = tid & 31;
    const int wm = wid >> 1, wn = wid & 1;
    const int g = lane >> 2, tq = lane & 3;
    const int m_base = blockIdx.y * 128;
    const int n_base = blockIdx.x * 128;
    const int z = blockIdx.z;

    const __half* A; const __half* Bt; const float* bias;
    int lda, K, Nrows, ldbk;
    if (MODE == 0) {
        A = g_xc + (size_t)m_base * DIMN; lda = DIMN; K = DIMN;
        if (z == 3) {
            if (blockIdx.x != 0) return;
            Bt = g_wint; Nrows = 64; ldbk = DIMN; bias = b_in;
        } else {
            Bt = (z == 0) ? g_wqt : (z == 1) ? g_wkt : g_wvt;
            Nrows = 512; ldbk = DIMN;
            bias = (z == 0) ? bq : (z == 1) ? bk : bv;
        }
    }
    if (MODE == 2) {
        A = g_h1 + (size_t)m_base * H1LD + z * DIN1; lda = H1LD; K = DIN1;
        Bt = g_w1t + (size_t)z * INTP * DIN1; Nrows = INTP; ldbk = DIN1;
        bias = b1 + z * INTER;
    }
    if (MODE == 3) {
        A = g_hs + (size_t)m_base * HSLDP; lda = HSLDP; K = HSLDP;
        Bt = g_w2t; Nrows = 512; ldbk = HSLDP; bias = b2;
    }

    float d[2][8][4];
#pragma unroll
    for (int i = 0; i < 2; i++)
#pragma unroll
        for (int j = 0; j < 8; j++)
#pragma unroll
            for (int c = 0; c < 4; c++) d[i][j][c] = 0.f;

    const int KT = (K + KC - 1) / KC;

    const int l8 = lane & 7, lm = lane >> 3;
    const uint32_t offA0 = (uint32_t)(((wm * 32 + (lm & 1) * 8 + l8) * LDH
                                       + (lm >> 1) * 8) * 2);
    const uint32_t offA1 = offA0 + (uint32_t)(16 * LDH * 2);
    uint32_t offB[4];
#pragma unroll
    for (int jj = 0; jj < 4; jj++)
        offB[jj] = (uint32_t)(((wn * 64 + jj * 16 + (lm >> 1) * 8 + l8) * LDH
                               + (lm & 1) * 8) * 2);

#define ISSUE(k0, buf)                                                         \
    do {                                                                       \
        uint32_t sA = smbase + (uint32_t)((buf) * BUFH) * 2u;                  \
        uint32_t sB = sA + (uint32_t)ABUFH * 2u;                               \
        _Pragma("unroll")                                                      \
        for (int i = 0; i < 4; i++) {                                          \
            int idx = tid + (i << 8);                                          \
            int row = idx >> 3, grp = idx & 7;                                 \
            int kk = (k0) + grp * 8;                                           \
            bool pk = kk < K;                                                  \
            int kcl = pk ? kk : 0;                                             \
            cp16(sA + (uint32_t)(row * LDH + grp * 8) * 2u,                    \
                 A + (size_t)row * lda + kcl, pk);                             \
            bool pb = pk && (n_base + row) < Nrows;                            \
            int brow = ((n_base + row) < Nrows) ? (n_base + row) : 0;          \
            cp16(sB + (uint32_t)(row * LDH + grp * 8) * 2u,                    \
                 Bt + (size_t)brow * ldbk + kcl, pb);                          \
        }                                                                      \
    } while (0)

    ISSUE(0, 0);
    CP_COMMIT();
    ISSUE(KC, 1);
    CP_COMMIT();
    CP_WAIT1();
    __syncthreads();

    for (int t = 0; t < KT; t++) {
        const uint32_t aB = smbase + (uint32_t)((t & 1) * BUFH) * 2u;
        const uint32_t bB = aB + (uint32_t)ABUFH * 2u;
#pragma unroll
        for (int ks = 0; ks < 4; ks++) {
            const uint32_t kof = (uint32_t)(ks * 32);
            uint32_t bf[8][2];
#pragma unroll
            for (int jj = 0; jj < 4; jj++)
                ldsm_x4(bf[2 * jj][0], bf[2 * jj][1],
                        bf[2 * jj + 1][0], bf[2 * jj + 1][1], bB + offB[jj] + kof);
            uint32_t af0[4], af1[4];
            ldsm_x4(af0[0], af0[1], af0[2], af0[3], aB + offA0 + kof);
            ldsm_x4(af1[0], af1[1], af1[2], af1[3], aB + offA1 + kof);
#pragma unroll
            for (int j = 0; j < 8; j++) {
                mma_f16(d[0][j], af0, bf[j]);
                mma_f16(d[1][j], af1, bf[j]);
            }
        }
        __syncthreads();
        if (t + 2 < KT) { ISSUE((t + 2) * KC, t & 1); CP_COMMIT(); }
        if (t + 1 < KT) {
            if (t + 2 < KT) CP_WAIT1(); else CP_WAIT0();
            __syncthreads();
        }
    }

    // ---------------- epilogue ----------------
#pragma unroll
    for (int i = 0; i < 2; i++) {
        int mr[2];
        mr[0] = m_base + wm * 32 + i * 16 + g;
        mr[1] = mr[0] + 8;
#pragma unroll
        for (int j = 0; j < 8; j++) {
            int n0 = n_base + wn * 64 + j * 8 + tq * 2;
#pragma unroll
            for (int rr = 0; rr < 2; rr++) {
                float v0 = d[i][j][rr * 2 + 0];
                float v1 = d[i][j][rr * 2 + 1];
                int m = mr[rr];
                if (MODE == 0) {
                    if (z == 3) {
                        if (n0 < 64) {
                            int r0i = n0 >> 4, d0i = n0 & 15;
                            int r1i = (n0 + 1) >> 4, d1i = (n0 + 1) & 15;
                            g_h1[(size_t)m * H1LD + r0i * DIN1 + 128 + d0i] =
                                __float2half_rn(v0 + bias[n0]);
                            g_h1[(size_t)m * H1LD + r1i * DIN1 + 128 + d1i] =
                                __float2half_rn(v1 + bias[n0 + 1]);
                        }
                    } else {
                        __half* C = g_qkv + (size_t)z * TOK * DIMN;
                        *(__half2*)(C + (size_t)m * DIMN + n0) =
                            __floats2half2_rn(v0 + bias[n0], v1 + bias[n0 + 1]);
                    }
                } else if (MODE == 2) {
                    float rsv = rs[m * RNUM + z];
                    size_t base = (size_t)m * HSLDP + z * INTP + n0;
                    if (n0 + 1 < INTER) {
                        *(__half2*)(g_hs + base) = __floats2half2_rn(
                            fmaxf(v0 + bias[n0], 0.f) * rsv,
                            fmaxf(v1 + bias[n0 + 1], 0.f) * rsv);
                    } else if (n0 < INTER) {
                        g_hs[base] = __float2half_rn(fmaxf(v0 + bias[n0], 0.f) * rsv);
                    }
                } else {
                    float4 q = *(const float4*)(rs + m * RNUM);
                    float b0 = q.x * bias[n0]            + q.y * bias[DIMN + n0]
                             + q.z * bias[2 * DIMN + n0] + q.w * bias[3 * DIMN + n0];
                    float b1v = q.x * bias[n0 + 1]            + q.y * bias[DIMN + n0 + 1]
                              + q.z * bias[2 * DIMN + n0 + 1] + q.w * bias[3 * DIMN + n0 + 1];
                    *(float2*)(out + (size_t)m * DIMN + n0) =
                        make_float2(v0 + b0, v1 + b1v);
                }
            }
        }
    }

    if (MODE == 3 && blockIdx.x == 0) {
        int idx = blockIdx.y * 512 + tid * 2;
        *(float2*)(out + (size_t)TOK * DIMN + idx) = *(const float2*)(rs + idx);
    }
#undef ISSUE
}

// ============================================================
// Flash attention, fp16 mma + ldmatrix + ex2 (R11), occupancy 3.
// ============================================================
#define LDQH 24
#define LDPH 136
#define FA_SMEM ((128 * LDQH * 2 + 16 * LDPH + 128 * LDPH) * 2)
#define QK_SCALE 0.360673760222241f   /* 0.25 * log2(e) */

__global__ void __launch_bounds__(256, 3) fa_kernel()
{
    extern __shared__ __half fsh[];
    __half* Qs = fsh;
    __half* Ks = fsh + 128 * LDQH;
    __half* Vs = fsh + 2 * 128 * LDQH;
    __half* Ps = Vs + 16 * LDPH;
    const uint32_t uQs = smem_u32(Qs);
    const uint32_t uKs = smem_u32(Ks);
    const uint32_t uVs = smem_u32(Vs);
    const uint32_t uPs = smem_u32(Ps);

    const int qt = blockIdx.x;
    const int gg = blockIdx.y;
    const int bb = blockIdx.z;
    const int r = gg >> 3, hh = gg & 7;
    const int tid = threadIdx.x;
    const int wid = tid >> 5, lane = tid & 31;
    const int g = lane >> 2, tq = lane & 3;
    const int l8 = lane & 7, lm = lane >> 3;

    const __half* gq = g_qkv;
    const __half* gk = g_qkv + (size_t)TOK * DIMN;
    const __half* gv = g_qkv + 2 * (size_t)TOK * DIMN;
    const int seq0 = bb * NSEQ;

    const __half2 qscale = __floats2half2_rn(QK_SCALE, QK_SCALE);

    {
        int row = tid >> 1, part = tid & 1;
        int tok = seq0 + qt * 128 + row;
        uint4 v = *(const uint4*)(gq + (size_t)tok * DIMN + gg * HD + part * 8);
        __half2* pv = (__half2*)&v;
#pragma unroll
        for (int l = 0; l < 4; l++) pv[l] = __hmul2(pv[l], qscale);
        *(uint4*)(Qs + row * LDQH + part * 8) = v;
    }

    float o[2][4];
#pragma unroll
    for (int j = 0; j < 2; j++)
#pragma unroll
        for (int c = 0; c < 4; c++) o[j][c] = 0.f;
    float lsum[2] = {0.f, 0.f};

    const int row0 = wid * 16 + g;

    const uint32_t offQA = (uint32_t)(((wid * 16 + (lm & 1) * 8 + l8) * LDQH
                                       + (lm >> 1) * 8) * 2);
    uint32_t offKB[4];
#pragma unroll
    for (int jj = 0; jj < 4; jj++)
        offKB[jj] = (uint32_t)(((jj * 16 + (lm >> 1) * 8 + l8) * LDQH
                                + (lm & 1) * 8) * 2);
    const uint32_t offPA = (uint32_t)(((wid * 16 + (lm & 1) * 8 + l8) * LDPH
                                       + (lm >> 1) * 8) * 2);
    const uint32_t offVB = (uint32_t)((((lm >> 1) * 8 + l8) * LDPH
                                       + (lm & 1) * 8) * 2);

    for (int jt = 0; jt < 4; jt++) {
        {
            int row = tid >> 1, part = tid & 1;
            int tok = seq0 + jt * 128 + row;
            uint4 kv = *(const uint4*)(gk + (size_t)tok * DIMN + gg * HD + part * 8);
            *(uint4*)(Ks + row * LDQH + part * 8) = kv;
            uint4 vv = *(const uint4*)(gv + (size_t)tok * DIMN + gg * HD + part * 8);
            __half tmp[8];
            *(uint4*)tmp = vv;
            int d0 = part * 8;
#pragma unroll
            for (int l = 0; l < 8; l++) Vs[(d0 + l) * LDPH + row] = tmp[l];
        }
        __syncthreads();

        uint32_t af[4];
        ldsm_x4(af[0], af[1], af[2], af[3], uQs + offQA);

#pragma unroll
        for (int hn = 0; hn < 2; hn++) {
            const uint32_t hof = (uint32_t)(hn * 64 * LDQH * 2);
            uint32_t bf[8][2];
#pragma unroll
            for (int jj = 0; jj < 4; jj++)
                ldsm_x4(bf[2 * jj][0], bf[2 * jj][1],
                        bf[2 * jj + 1][0], bf[2 * jj + 1][1],
                        uKs + offKB[jj] + hof);
            float s[8][4];
#pragma unroll
            for (int jn = 0; jn < 8; jn++) {
#pragma unroll
                for (int c = 0; c < 4; c++) s[jn][c] = 0.f;
                mma_f16(s[jn], af, bf[jn]);
            }
#pragma unroll
            for (int jn = 0; jn < 8; jn++) {
                int c0 = hn * 64 + jn * 8 + 2 * tq;
                int gc0 = jt * 128 + c0;
#pragma unroll
                for (int rr = 0; rr < 2; rr++) {
                    int rl = row0 + rr * 8;
                    int grow = qt * 128 + rl;
                    float p0 = ex2(s[jn][rr * 2 + 0]);
                    float p1 = ex2(s[jn][rr * 2 + 1]);
                    if (gc0 == grow)     p0 = 0.f;
                    if (gc0 + 1 == grow) p1 = 0.f;
                    lsum[rr] += p0 + p1;
                    *(__half2*)(Ps + rl * LDPH + c0) = __floats2half2_rn(p0, p1);
                }
            }
        }
        __syncthreads();

#pragma unroll
        for (int ksi = 0; ksi < 8; ksi++) {
            const uint32_t kof = (uint32_t)(ksi * 32);
            uint32_t pa[4];
            ldsm_x4(pa[0], pa[1], pa[2], pa[3], uPs + offPA + kof);
            uint32_t bf[2][2];
            ldsm_x4(bf[0][0], bf[0][1], bf[1][0], bf[1][1], uVs + offVB + kof);
            mma_f16(o[0], pa, bf[0]);
            mma_f16(o[1], pa, bf[1]);
        }
        __syncthreads();
    }

#pragma unroll
    for (int rr = 0; rr < 2; rr++) {
        lsum[rr] += __shfl_xor_sync(0xFFFFFFFF, lsum[rr], 1);
        lsum[rr] += __shfl_xor_sync(0xFFFFFFFF, lsum[rr], 2);
    }
    float inv[2] = {1.f / lsum[0], 1.f / lsum[1]};

#pragma unroll
    for (int rr = 0; rr < 2; rr++) {
        int tok = seq0 + qt * 128 + row0 + rr * 8;
        __half* dst = g_h1 + (size_t)tok * H1LD + r * DIN1 + hh * HD;
#pragma unroll
        for (int jn = 0; jn < 2; jn++) {
            int col = jn * 8 + 2 * tq;
            *(__half2*)(dst + col) = __floats2half2_rn(o[jn][rr * 2 + 0] * inv[rr],
                                                       o[jn][rr * 2 + 1] * inv[rr]);
        }
    }
}

// ============================================================
extern "C" void kernel_launch(void* const* d_in, const int* in_sizes, int n_in,
                              void* d_out, int out_size)
{
    const float* x    = (const float*)d_in[0];
    const float* rs   = (const float*)d_in[1];
    const float* Wq   = (const float*)d_in[2];
    const float* bq   = (const float*)d_in[3];
    const float* Wk   = (const float*)d_in[4];
    const float* bk   = (const float*)d_in[5];
    const float* Wv   = (const float*)d_in[6];
    const float* bv   = (const float*)d_in[7];
    const float* Win  = (const float*)d_in[8];
    const float* b_in = (const float*)d_in[9];
    const float* W1   = (const float*)d_in[10];
    const float* b1   = (const float*)d_in[11];
    const float* W2   = (const float*)d_in[12];
    const float* b2   = (const float*)d_in[13];
    float* out = (float*)d_out;

    cudaFuncSetAttribute(mma_gemm<0>, cudaFuncAttributeMaxDynamicSharedMemorySize, GEMM_SMEM);
    cudaFuncSetAttribute(mma_gemm<2>, cudaFuncAttributeMaxDynamicSharedMemorySize, GEMM_SMEM);
    cudaFuncSetAttribute(mma_gemm<3>, cudaFuncAttributeMaxDynamicSharedMemorySize, GEMM_SMEM);
    cudaFuncSetAttribute(fa_kernel, cudaFuncAttributeMaxDynamicSharedMemorySize, FA_SMEM);

    conv_all<<<2132, 256>>>(x, Wq, Wk, Wv, Win, W1, W2);

    mma_gemm<0><<<dim3(4, 32, 4), 256, GEMM_SMEM>>>(bq, bk, bv, b_in, b1, b2, rs, out);
    fa_kernel<<<dim3(4, GQ, 8), 256, FA_SMEM>>>();
    mma_gemm<2><<<dim3(4, 32, 4), 256, GEMM_SMEM>>>(bq, bk, bv, b_in, b1, b2, rs, out);
    mma_gemm<3><<<dim3(4, 32, 1), 256, GEMM_SMEM>>>(bq, bk, bv, b_in, b1, b2, rs, out);
}